// round 15
// baseline (speedup 1.0000x reference)
#include <cuda_runtime.h>
#include <cuda_fp16.h>
#include <cstdint>

#define D_FEAT 64
#define TILE_M 128
#define NTHREADS 256
#define K_CLUSTERS 512
#define INV_T 10.0f
#define LOG2E 1.4426950408889634f

// smem byte offsets — single fp16 plane per GEMM, ALL 512 clusters resident
#define SM_G1 0            // GEMM1 B fragments (fp16, packed)  64KB
#define SM_G2 65536        // GEMM2 B fragments (fp16, packed)  64KB
#define SM_BIAS 131072     // 512 floats                        2KB
#define SM_TOTAL 133120

typedef unsigned int u32;

__device__ __forceinline__ u32 s2u(const void* p) {
    u32 a;
    asm("{ .reg .u64 t; cvta.to.shared.u64 t, %1; cvt.u32.u64 %0, t; }" : "=r"(a) : "l"(p));
    return a;
}
__device__ __forceinline__ void lds128(u32 addr, u32& q0, u32& q1, u32& q2, u32& q3) {
    asm volatile("ld.shared.v4.b32 {%0,%1,%2,%3}, [%4];"
                 : "=r"(q0), "=r"(q1), "=r"(q2), "=r"(q3) : "r"(addr));
}
__device__ __forceinline__ float ex2f(float v) {
    float y; asm("ex2.approx.ftz.f32 %0, %1;" : "=f"(y) : "f"(v)); return y;
}
// pack (lo, hi) floats -> f16x2 with lo in the LOW half
__device__ __forceinline__ u32 f2h2(float lo, float hi) {
    u32 r; asm("cvt.rn.f16x2.f32 %0, %1, %2;" : "=r"(r) : "f"(hi), "f"(lo)); return r;
}
__device__ __forceinline__ float2 unh2(u32 v) {
    __half2 h = *reinterpret_cast<__half2*>(&v);
    return __half22float2(h);
}
// fp16 hi split + fp16 residual split (22 effective bits)
__device__ __forceinline__ u32 f16r(float a, float b, u32& lo) {
    const u32 h = f2h2(a, b);
    const float2 f = unh2(h);
    lo = f2h2(a - f.x, b - f.y);
    return h;
}
// D += A*B, m16n8k16 fp16 in, f32 accum
__device__ __forceinline__ void mma16816(float* d, const u32* a, u32 b0, u32 b1) {
    asm volatile("mma.sync.aligned.m16n8k16.row.col.f32.f16.f16.f32 "
                 "{%0,%1,%2,%3}, {%4,%5,%6,%7}, {%8,%9}, {%0,%1,%2,%3};"
                 : "+f"(d[0]), "+f"(d[1]), "+f"(d[2]), "+f"(d[3])
                 : "r"(a[0]), "r"(a[1]), "r"(a[2]), "r"(a[3]), "r"(b0), "r"(b1));
}

// GEMM1: one k-slice s of one 64-cluster sub into S (2-term fp16)
__device__ __forceinline__ void g1slice(u32 g1b, int sub, int s, float S[8][4],
                                        const u32 Ah[4][4], const u32 Al[4][4]) {
    const u32 base = g1b + (u32)sub * 8192 + (u32)s * 2048;
    #pragma unroll
    for (int nbp = 0; nbp < 4; nbp++) {
        u32 q0, q1, q2, q3;
        lds128(base + nbp * 512, q0, q1, q2, q3);
        mma16816(S[2 * nbp],     Ah[s], q0, q1);
        mma16816(S[2 * nbp],     Al[s], q0, q1);
        mma16816(S[2 * nbp + 1], Ah[s], q2, q3);
        mma16816(S[2 * nbp + 1], Al[s], q2, q3);
    }
}
// GEMM2: one k16 slice t of one sub into O (2-term fp16 via W chaining)
__device__ __forceinline__ void g2slice(u32 g2b, int sub, int t, const u32 Wh[4],
                                        const u32 Wl[4], float O[8][4]) {
    const u32 base = g2b + (u32)sub * 8192 + (u32)t * 2048;
    #pragma unroll
    for (int nbp2 = 0; nbp2 < 4; nbp2++) {
        u32 q0, q1, q2, q3;
        lds128(base + nbp2 * 512, q0, q1, q2, q3);
        mma16816(O[2 * nbp2],     Wh, q0, q1);
        mma16816(O[2 * nbp2],     Wl, q0, q1);
        mma16816(O[2 * nbp2 + 1], Wh, q2, q3);
        mma16816(O[2 * nbp2 + 1], Wl, q2, q3);
    }
}

__global__ void __launch_bounds__(NTHREADS, 1)
kmeans_hmma12_kernel(const float* __restrict__ x,
                     const float* __restrict__ centroids,
                     float* __restrict__ out,
                     int n_tiles)
{
    extern __shared__ char smem[];
    const u32 sb = s2u(smem);
    const int tid = threadIdx.x;
    const int lane = tid & 31;
    const int wid = tid >> 5;
    const int gid = lane >> 2;
    const int tg = lane & 3;
    const int m0 = wid * 16;

    const float SC = 2.0f * INV_T * LOG2E;
    const u32 g1b = sb + SM_G1 + (u32)lane * 16;
    const u32 g2b = sb + SM_G2 + (u32)lane * 16;

    // ---- prologue (once): fp16 fragment-packed B tables for both GEMMs + bias ----
    {
        const float4* C4 = reinterpret_cast<const float4*>(centroids);
        const float BSCALE = INV_T * LOG2E;
        #pragma unroll 1
        for (int i = tid; i < K_CLUSTERS * 16; i += NTHREADS) {   // 8192
            const float4 v = C4[i];
            const int cl = i >> 4;                 // cluster 0..511
            const int dq = i & 15;                 // float4 index in row
            float vf[4] = {v.x, v.y, v.z, v.w};
            const int sub = cl >> 6;               // 0..7
            const int nb = (cl >> 3) & 7, gids = cl & 7;
            const int nbp = nb >> 1, odd = nb & 1;
            const int rr = cl & 63, t2 = rr >> 4, q2 = rr & 15;
            const int reg2 = (q2 >> 3) & 1, tgs2 = (q2 & 7) >> 1, el2 = q2 & 1;
            #pragma unroll
            for (int e = 0; e < 4; e++) {
                const int d = 4 * dq + e;
                const __half hv = __float2half_rn(vf[e]);
                // G1: k = feat, n = cluster
                {
                    const int s = d >> 4, r = d & 15;
                    const int reg = (r >> 3) & 1, tgs = (r & 7) >> 1, el = r & 1;
                    const u32 off = (u32)(((sub * 16 + s * 4 + nbp) * 32 + gids * 4 + tgs) * 16
                                          + odd * 8 + reg * 4 + el * 2);
                    *reinterpret_cast<__half*>(smem + SM_G1 + off) = hv;
                }
                // G2: k = cluster, n = feat
                {
                    const int nb2 = d >> 3, gids2 = d & 7;
                    const int nbp2 = nb2 >> 1, odd2 = nb2 & 1;
                    const u32 off = (u32)(((sub * 16 + t2 * 4 + nbp2) * 32 + gids2 * 4 + tgs2) * 16
                                          + odd2 * 8 + reg2 * 4 + el2 * 2);
                    *reinterpret_cast<__half*>(smem + SM_G2 + off) = hv;
                }
            }
            float p = v.x * v.x + v.y * v.y + v.z * v.z + v.w * v.w;
            p += __shfl_xor_sync(0xFFFFFFFF, p, 1);
            p += __shfl_xor_sync(0xFFFFFFFF, p, 2);
            p += __shfl_xor_sync(0xFFFFFFFF, p, 4);
            p += __shfl_xor_sync(0xFFFFFFFF, p, 8);
            if ((lane & 15) == 0)
                *reinterpret_cast<float*>(smem + SM_BIAS + cl * 4) = p * BSCALE;
        }
    }
    __syncthreads();   // tables read-only from here: no further syncs needed

    // ---- tile loop: single pass over ALL 512 clusters per tile ----
    #pragma unroll 1
    for (int tile = blockIdx.x; tile < n_tiles; tile += gridDim.x) {
        // A fragments from gmem: X as fp16 hi + fp16 residual (PTX spec positions)
        u32 Ah[4][4], Al[4][4];
        {
            const float* xb = x + ((size_t)tile * TILE_M + m0 + gid) * D_FEAT;
            #pragma unroll
            for (int s = 0; s < 4; s++) {
                const int c0 = 16 * s + 2 * tg;
                const float2 v0 = *reinterpret_cast<const float2*>(xb + c0);
                const float2 v1 = *reinterpret_cast<const float2*>(xb + 8 * D_FEAT + c0);
                const float2 v2 = *reinterpret_cast<const float2*>(xb + c0 + 8);
                const float2 v3 = *reinterpret_cast<const float2*>(xb + 8 * D_FEAT + c0 + 8);
                Ah[s][0] = f16r(v0.x, v0.y, Al[s][0]);
                Ah[s][1] = f16r(v1.x, v1.y, Al[s][1]);
                Ah[s][2] = f16r(v2.x, v2.y, Al[s][2]);
                Ah[s][3] = f16r(v3.x, v3.y, Al[s][3]);
            }
        }

        float O[8][4];
        #pragma unroll
        for (int n = 0; n < 8; n++)
            #pragma unroll
            for (int e = 0; e < 4; e++) O[n][e] = 0.f;
        float sum0 = 0.f, sum1 = 0.f;
        float M0 = -1e30f, M1 = -1e30f;      // running row maxes (log2 units)

        // double-buffered logits stage
        float S[2][8][4];
        #pragma unroll
        for (int n = 0; n < 8; n++)
            #pragma unroll
            for (int e = 0; e < 4; e++) S[0][n][e] = 0.f;
        #pragma unroll
        for (int s = 0; s < 4; s++) g1slice(g1b, 0, s, S[0], Ah, Al);

        #pragma unroll
        for (int i = 0; i < 8; i++) {            // 8 x 64-cluster sub-chunks
            const int cur = i & 1, nxt = cur ^ 1;
            float (*Sc)[4] = S[cur];
            float (*Sn)[4] = S[nxt];

            // start next sub's GEMM1 (slices 0-1) BEFORE the epilogue: keeps
            // the tensor pipe fed through the MUFU/CVT chain below
            if (i < 7) {
                #pragma unroll
                for (int n = 0; n < 8; n++)
                    #pragma unroll
                    for (int e = 0; e < 4; e++) Sn[n][e] = 0.f;
                g1slice(g1b, i + 1, 0, Sn, Ah, Al);
                g1slice(g1b, i + 1, 1, Sn, Ah, Al);
            }

            // ---- epilogue on current sub: logits (log2 units) ----
            #pragma unroll
            for (int nb = 0; nb < 8; nb++) {
                const int coll = i * 64 + nb * 8 + 2 * tg;
                const float2 bb = *reinterpret_cast<const float2*>(smem + SM_BIAS + coll * 4);
                Sc[nb][0] = fmaf(Sc[nb][0], SC, -bb.x);
                Sc[nb][1] = fmaf(Sc[nb][1], SC, -bb.y);
                Sc[nb][2] = fmaf(Sc[nb][2], SC, -bb.x);
                Sc[nb][3] = fmaf(Sc[nb][3], SC, -bb.y);
            }
            // chunk row maxes + running-max update (flash style)
            float m0c = Sc[0][0], m1c = Sc[0][2];
            #pragma unroll
            for (int nb = 0; nb < 8; nb++) {
                m0c = fmaxf(m0c, fmaxf(Sc[nb][0], Sc[nb][1]));
                m1c = fmaxf(m1c, fmaxf(Sc[nb][2], Sc[nb][3]));
            }
            m0c = fmaxf(m0c, __shfl_xor_sync(0xFFFFFFFF, m0c, 1));
            m0c = fmaxf(m0c, __shfl_xor_sync(0xFFFFFFFF, m0c, 2));
            m1c = fmaxf(m1c, __shfl_xor_sync(0xFFFFFFFF, m1c, 1));
            m1c = fmaxf(m1c, __shfl_xor_sync(0xFFFFFFFF, m1c, 2));
            const float M0n = fmaxf(M0, m0c);
            const float M1n = fmaxf(M1, m1c);
            const float sc0 = ex2f(M0 - M0n);    // <= 1, exact power of 2
            const float sc1 = ex2f(M1 - M1n);
            M0 = M0n; M1 = M1n;
            sum0 *= sc0; sum1 *= sc1;
            #pragma unroll
            for (int n = 0; n < 8; n++) {
                O[n][0] *= sc0; O[n][1] *= sc0;
                O[n][2] *= sc1; O[n][3] *= sc1;
            }
            // weights w = 2^(S - M) in (0, 1]
            #pragma unroll
            for (int nb = 0; nb < 8; nb++) {
                Sc[nb][0] = ex2f(Sc[nb][0] - M0);
                Sc[nb][1] = ex2f(Sc[nb][1] - M0);
                Sc[nb][2] = ex2f(Sc[nb][2] - M1);
                Sc[nb][3] = ex2f(Sc[nb][3] - M1);
                sum0 += Sc[nb][0] + Sc[nb][1];
                sum1 += Sc[nb][2] + Sc[nb][3];
            }

            // ---- GEMM2 t-loop, with next-sub GEMM1 slices 2-3 interleaved ----
            #pragma unroll
            for (int t = 0; t < 4; t++) {
                u32 Wh[4], Wl[4];
                Wh[0] = f16r(Sc[2*t][0],   Sc[2*t][1],   Wl[0]);
                Wh[1] = f16r(Sc[2*t][2],   Sc[2*t][3],   Wl[1]);
                Wh[2] = f16r(Sc[2*t+1][0], Sc[2*t+1][1], Wl[2]);
                Wh[3] = f16r(Sc[2*t+1][2], Sc[2*t+1][3], Wl[3]);
                if (i < 7 && (t == 1 || t == 2))
                    g1slice(g1b, i + 1, t + 1, Sn, Ah, Al);
                g2slice(g2b, i, t, Wh, Wl, O);
            }
        }

        // normalize + single store (scale factors cancel between O and sum)
        sum0 += __shfl_xor_sync(0xFFFFFFFF, sum0, 1);
        sum0 += __shfl_xor_sync(0xFFFFFFFF, sum0, 2);
        sum1 += __shfl_xor_sync(0xFFFFFFFF, sum1, 1);
        sum1 += __shfl_xor_sync(0xFFFFFFFF, sum1, 2);
        const float inv0 = __frcp_rn(sum0);
        const float inv1 = __frcp_rn(sum1);

        float* op = out + ((size_t)tile * TILE_M) * D_FEAT;
        const int r0 = m0 + gid;
        const int r1 = r0 + 8;
        #pragma unroll
        for (int n = 0; n < 8; n++) {
            const int col = 8 * n + 2 * tg;
            *reinterpret_cast<float2*>(op + r0 * D_FEAT + col) =
                make_float2(O[n][0] * inv0, O[n][1] * inv0);
            *reinterpret_cast<float2*>(op + r1 * D_FEAT + col) =
                make_float2(O[n][2] * inv1, O[n][3] * inv1);
        }
    }
}

extern "C" void kernel_launch(void* const* d_in, const int* in_sizes, int n_in,
                              void* d_out, int out_size)
{
    const float* x = (const float*)d_in[0];
    const float* centroids = (const float*)d_in[1];
    float* out = (float*)d_out;

    const int n_points = in_sizes[0] / D_FEAT;   // 131072
    const int n_tiles = n_points / TILE_M;       // 1024

    static bool attr_set = false;
    if (!attr_set) {
        cudaFuncSetAttribute(kmeans_hmma12_kernel,
                             cudaFuncAttributeMaxDynamicSharedMemorySize, SM_TOTAL);
        attr_set = true;
    }

    const int grid = (n_tiles < 148) ? n_tiles : 148;
    kmeans_hmma12_kernel<<<grid, NTHREADS, SM_TOTAL>>>(x, centroids, out, n_tiles);
}

// round 16
// speedup vs baseline: 1.2482x; 1.2482x over previous
#include <cuda_runtime.h>
#include <cuda_fp16.h>
#include <cstdint>

#define D_FEAT 64
#define TILE_M 128
#define NTHREADS 256
#define K_CLUSTERS 512
#define INV_T 10.0f
#define LOG2E 1.4426950408889634f

// smem byte offsets — single fp16 plane per GEMM, ALL 512 clusters resident
#define SM_G1 0            // GEMM1 B fragments (fp16, packed)  64KB
#define SM_G2 65536        // GEMM2 B fragments (fp16, packed)  64KB
#define SM_BIAS 131072     // 512 floats                        2KB
#define SM_TOTAL 133120

typedef unsigned int u32;

__device__ __forceinline__ u32 s2u(const void* p) {
    u32 a;
    asm("{ .reg .u64 t; cvta.to.shared.u64 t, %1; cvt.u32.u64 %0, t; }" : "=r"(a) : "l"(p));
    return a;
}
__device__ __forceinline__ void lds128(u32 addr, u32& q0, u32& q1, u32& q2, u32& q3) {
    asm volatile("ld.shared.v4.b32 {%0,%1,%2,%3}, [%4];"
                 : "=r"(q0), "=r"(q1), "=r"(q2), "=r"(q3) : "r"(addr));
}
__device__ __forceinline__ float ex2f(float v) {
    float y; asm("ex2.approx.ftz.f32 %0, %1;" : "=f"(y) : "f"(v)); return y;
}
// pack (lo, hi) floats -> f16x2 with lo in the LOW half
__device__ __forceinline__ u32 f2h2(float lo, float hi) {
    u32 r; asm("cvt.rn.f16x2.f32 %0, %1, %2;" : "=r"(r) : "f"(hi), "f"(lo)); return r;
}
__device__ __forceinline__ float2 unh2(u32 v) {
    __half2 h = *reinterpret_cast<__half2*>(&v);
    return __half22float2(h);
}
// fp16 hi split + fp16 residual split (22 effective bits)
__device__ __forceinline__ u32 f16r(float a, float b, u32& lo) {
    const u32 h = f2h2(a, b);
    const float2 f = unh2(h);
    lo = f2h2(a - f.x, b - f.y);
    return h;
}
// D += A*B, m16n8k16 fp16 in, f32 accum
__device__ __forceinline__ void mma16816(float* d, const u32* a, u32 b0, u32 b1) {
    asm volatile("mma.sync.aligned.m16n8k16.row.col.f32.f16.f16.f32 "
                 "{%0,%1,%2,%3}, {%4,%5,%6,%7}, {%8,%9}, {%0,%1,%2,%3};"
                 : "+f"(d[0]), "+f"(d[1]), "+f"(d[2]), "+f"(d[3])
                 : "r"(a[0]), "r"(a[1]), "r"(a[2]), "r"(a[3]), "r"(b0), "r"(b1));
}

__global__ void __launch_bounds__(NTHREADS, 1)
kmeans_hmma13_kernel(const float* __restrict__ x,
                     const float* __restrict__ centroids,
                     float* __restrict__ out,
                     int n_tiles)
{
    extern __shared__ char smem[];
    const u32 sb = s2u(smem);
    const int tid = threadIdx.x;
    const int lane = tid & 31;
    const int wid = tid >> 5;
    const int gid = lane >> 2;
    const int tg = lane & 3;
    const int m0 = wid * 16;

    const float SC = 2.0f * INV_T * LOG2E;
    const u32 g1b = sb + SM_G1 + (u32)lane * 16;
    const u32 g2b = sb + SM_G2 + (u32)lane * 16;

    // ---- prologue (once): fp16 fragment-packed B tables for both GEMMs + bias ----
    // 16B slot covers an nb-PAIR: {nb even: b0,b1 | nb odd: b0,b1}
    {
        const float4* C4 = reinterpret_cast<const float4*>(centroids);
        const float BSCALE = INV_T * LOG2E;
        #pragma unroll 1
        for (int i = tid; i < K_CLUSTERS * 16; i += NTHREADS) {   // 8192
            const float4 v = C4[i];
            const int cl = i >> 4;                 // cluster 0..511
            const int dq = i & 15;                 // float4 index in row
            float vf[4] = {v.x, v.y, v.z, v.w};
            const int sub = cl >> 6;               // 0..7
            const int nb = (cl >> 3) & 7, gids = cl & 7;
            const int nbp = nb >> 1, odd = nb & 1;
            const int rr = cl & 63, t2 = rr >> 4, q2 = rr & 15;
            const int reg2 = (q2 >> 3) & 1, tgs2 = (q2 & 7) >> 1, el2 = q2 & 1;
            #pragma unroll
            for (int e = 0; e < 4; e++) {
                const int d = 4 * dq + e;
                const __half hv = __float2half_rn(vf[e]);
                // G1: k = feat, n = cluster
                {
                    const int s = d >> 4, r = d & 15;
                    const int reg = (r >> 3) & 1, tgs = (r & 7) >> 1, el = r & 1;
                    const u32 off = (u32)(((sub * 16 + s * 4 + nbp) * 32 + gids * 4 + tgs) * 16
                                          + odd * 8 + reg * 4 + el * 2);
                    *reinterpret_cast<__half*>(smem + SM_G1 + off) = hv;
                }
                // G2: k = cluster, n = feat
                {
                    const int nb2 = d >> 3, gids2 = d & 7;
                    const int nbp2 = nb2 >> 1, odd2 = nb2 & 1;
                    const u32 off = (u32)(((sub * 16 + t2 * 4 + nbp2) * 32 + gids2 * 4 + tgs2) * 16
                                          + odd2 * 8 + reg2 * 4 + el2 * 2);
                    *reinterpret_cast<__half*>(smem + SM_G2 + off) = hv;
                }
            }
            float p = v.x * v.x + v.y * v.y + v.z * v.z + v.w * v.w;
            p += __shfl_xor_sync(0xFFFFFFFF, p, 1);
            p += __shfl_xor_sync(0xFFFFFFFF, p, 2);
            p += __shfl_xor_sync(0xFFFFFFFF, p, 4);
            p += __shfl_xor_sync(0xFFFFFFFF, p, 8);
            if ((lane & 15) == 0)
                *reinterpret_cast<float*>(smem + SM_BIAS + cl * 4) = p * BSCALE;
        }
    }
    __syncthreads();   // tables read-only from here: no further syncs needed

    // ---- tile loop: single pass over ALL 512 clusters per tile ----
    #pragma unroll 1
    for (int tile = blockIdx.x; tile < n_tiles; tile += gridDim.x) {
        // A fragments from gmem: X as fp16 hi + fp16 residual (PTX spec positions)
        u32 Ah[4][4], Al[4][4];
        {
            const float* xb = x + ((size_t)tile * TILE_M + m0 + gid) * D_FEAT;
            #pragma unroll
            for (int s = 0; s < 4; s++) {
                const int c0 = 16 * s + 2 * tg;
                const float2 v0 = *reinterpret_cast<const float2*>(xb + c0);
                const float2 v1 = *reinterpret_cast<const float2*>(xb + 8 * D_FEAT + c0);
                const float2 v2 = *reinterpret_cast<const float2*>(xb + c0 + 8);
                const float2 v3 = *reinterpret_cast<const float2*>(xb + 8 * D_FEAT + c0 + 8);
                Ah[s][0] = f16r(v0.x, v0.y, Al[s][0]);
                Ah[s][1] = f16r(v1.x, v1.y, Al[s][1]);
                Ah[s][2] = f16r(v2.x, v2.y, Al[s][2]);
                Ah[s][3] = f16r(v3.x, v3.y, Al[s][3]);
            }
        }

        float O[8][4];
        #pragma unroll
        for (int n = 0; n < 8; n++)
            #pragma unroll
            for (int e = 0; e < 4; e++) O[n][e] = 0.f;
        float sum0 = 0.f, sum1 = 0.f;
        float M0 = -1e30f, M1 = -1e30f;      // running row maxes (log2 units)

        #pragma unroll 1
        for (int sub = 0; sub < 8; sub++) {      // 8 x 64-cluster sub-chunks
            const u32 so1 = g1b + (u32)sub * 8192;
            const u32 so2 = g2b + (u32)sub * 8192;
            float S[8][4];
            #pragma unroll
            for (int n = 0; n < 8; n++)
                #pragma unroll
                for (int e = 0; e < 4; e++) S[n][e] = 0.f;

            // GEMM1: 2-term fp16 (Xh*C + Xl*C); 1 LDS.128 feeds 4 HMMAs
            #pragma unroll
            for (int s = 0; s < 4; s++) {
                const u32 base = so1 + (u32)s * 2048;
                #pragma unroll
                for (int nbp = 0; nbp < 4; nbp++) {
                    u32 q0, q1, q2, q3;
                    lds128(base + nbp * 512, q0, q1, q2, q3);
                    mma16816(S[2 * nbp],     Ah[s], q0, q1);
                    mma16816(S[2 * nbp],     Al[s], q0, q1);
                    mma16816(S[2 * nbp + 1], Ah[s], q2, q3);
                    mma16816(S[2 * nbp + 1], Al[s], q2, q3);
                }
            }

            // ---- logits (log2 units) ----
            #pragma unroll
            for (int nb = 0; nb < 8; nb++) {
                const int coll = sub * 64 + nb * 8 + 2 * tg;
                const float2 bb = *reinterpret_cast<const float2*>(smem + SM_BIAS + coll * 4);
                S[nb][0] = fmaf(S[nb][0], SC, -bb.x);
                S[nb][1] = fmaf(S[nb][1], SC, -bb.y);
                S[nb][2] = fmaf(S[nb][2], SC, -bb.x);
                S[nb][3] = fmaf(S[nb][3], SC, -bb.y);
            }
            // ---- chunk row maxes + running-max update (flash style) ----
            float m0c = S[0][0], m1c = S[0][2];
            #pragma unroll
            for (int nb = 0; nb < 8; nb++) {
                m0c = fmaxf(m0c, fmaxf(S[nb][0], S[nb][1]));
                m1c = fmaxf(m1c, fmaxf(S[nb][2], S[nb][3]));
            }
            m0c = fmaxf(m0c, __shfl_xor_sync(0xFFFFFFFF, m0c, 1));
            m0c = fmaxf(m0c, __shfl_xor_sync(0xFFFFFFFF, m0c, 2));
            m1c = fmaxf(m1c, __shfl_xor_sync(0xFFFFFFFF, m1c, 1));
            m1c = fmaxf(m1c, __shfl_xor_sync(0xFFFFFFFF, m1c, 2));
            const float M0n = fmaxf(M0, m0c);
            const float M1n = fmaxf(M1, m1c);
            const float sc0 = ex2f(M0 - M0n);    // <= 1, exact power of 2
            const float sc1 = ex2f(M1 - M1n);
            M0 = M0n; M1 = M1n;
            sum0 *= sc0; sum1 *= sc1;
            #pragma unroll
            for (int n = 0; n < 8; n++) {
                O[n][0] *= sc0; O[n][1] *= sc0;
                O[n][2] *= sc1; O[n][3] *= sc1;
            }
            // ---- weights w = 2^(S - M) in (0, 1] ----
            #pragma unroll
            for (int nb = 0; nb < 8; nb++) {
                S[nb][0] = ex2f(S[nb][0] - M0);
                S[nb][1] = ex2f(S[nb][1] - M0);
                S[nb][2] = ex2f(S[nb][2] - M1);
                S[nb][3] = ex2f(S[nb][3] - M1);
                sum0 += S[nb][0] + S[nb][1];
                sum1 += S[nb][2] + S[nb][3];
            }

            // GEMM2: 1-term fp16 (Wh*C) via accum->A chaining — the W residual
            // plane protects only ~1.2e-4 of output error; dropped for 25% fewer HMMAs
            #pragma unroll
            for (int t = 0; t < 4; t++) {
                u32 Wh[4];
                Wh[0] = f2h2(S[2*t][0],   S[2*t][1]);
                Wh[1] = f2h2(S[2*t][2],   S[2*t][3]);
                Wh[2] = f2h2(S[2*t+1][0], S[2*t+1][1]);
                Wh[3] = f2h2(S[2*t+1][2], S[2*t+1][3]);
                const u32 base = so2 + (u32)t * 2048;
                #pragma unroll
                for (int nbp2 = 0; nbp2 < 4; nbp2++) {
                    u32 q0, q1, q2, q3;
                    lds128(base + nbp2 * 512, q0, q1, q2, q3);
                    mma16816(O[2 * nbp2],     Wh, q0, q1);
                    mma16816(O[2 * nbp2 + 1], Wh, q2, q3);
                }
            }
        }

        // normalize + single store (scale factors cancel between O and sum)
        sum0 += __shfl_xor_sync(0xFFFFFFFF, sum0, 1);
        sum0 += __shfl_xor_sync(0xFFFFFFFF, sum0, 2);
        sum1 += __shfl_xor_sync(0xFFFFFFFF, sum1, 1);
        sum1 += __shfl_xor_sync(0xFFFFFFFF, sum1, 2);
        const float inv0 = __frcp_rn(sum0);
        const float inv1 = __frcp_rn(sum1);

        float* op = out + ((size_t)tile * TILE_M) * D_FEAT;
        const int r0 = m0 + gid;
        const int r1 = r0 + 8;
        #pragma unroll
        for (int n = 0; n < 8; n++) {
            const int col = 8 * n + 2 * tg;
            *reinterpret_cast<float2*>(op + r0 * D_FEAT + col) =
                make_float2(O[n][0] * inv0, O[n][1] * inv0);
            *reinterpret_cast<float2*>(op + r1 * D_FEAT + col) =
                make_float2(O[n][2] * inv1, O[n][3] * inv1);
        }
    }
}

extern "C" void kernel_launch(void* const* d_in, const int* in_sizes, int n_in,
                              void* d_out, int out_size)
{
    const float* x = (const float*)d_in[0];
    const float* centroids = (const float*)d_in[1];
    float* out = (float*)d_out;

    const int n_points = in_sizes[0] / D_FEAT;   // 131072
    const int n_tiles = n_points / TILE_M;       // 1024

    static bool attr_set = false;
    if (!attr_set) {
        cudaFuncSetAttribute(kmeans_hmma13_kernel,
                             cudaFuncAttributeMaxDynamicSharedMemorySize, SM_TOTAL);
        attr_set = true;
    }

    const int grid = (n_tiles < 148) ? n_tiles : 148;
    kmeans_hmma13_kernel<<<grid, NTHREADS, SM_TOTAL>>>(x, centroids, out, n_tiles);
}